// round 2
// baseline (speedup 1.0000x reference)
#include <cuda_runtime.h>
#include <cstdint>

#define N_NODES 50000
#define N_EDGES 800000
#define D 128
#define N_GRAPHS 512
#define N_CONVS 5
#define EPS 1e-5f

typedef unsigned long long u64;

// ---------------- scratch (static device globals; no allocation) -------------
__device__ int   g_cnt[N_NODES];
__device__ int   g_cur[N_NODES];
__device__ int   g_off[N_NODES + 1];
__device__ int   g_ssrc[N_EDGES];
__device__ float g_agg[(size_t)N_NODES * D];
__device__ float g_h[(size_t)N_NODES * D];
__device__ float g_B[256 * D];     // folded weights, k-major: B[k][j]
__device__ float g_br[D];          // folded bias
__device__ float g_bnsum[D];
__device__ float g_bnsq[D];
__device__ float g_scale[D];
__device__ float g_shift[D];
__device__ float g_pmax[N_GRAPHS * D];
__device__ float g_pmin[N_GRAPHS * D];

// ---------------- K0: init + weight folding ---------------------------------
// ranges: [0,50000) cnt=0 | [50000,100000) cur=0 | [100000,132768) fold B
//         [132768,132896) fold br | [132896,133152) zero bn stats
#define INIT_TOTAL (2 * N_NODES + 256 * D + D + 2 * D)
__global__ void k_init(const float* __restrict__ Wrel,
                       const float* __restrict__ brel,
                       const float* __restrict__ Wroot) {
    int idx = blockIdx.x * blockDim.x + threadIdx.x;
    if (idx < N_NODES) {
        g_cnt[idx] = 0;
    } else if (idx < 2 * N_NODES) {
        g_cur[idx - N_NODES] = 0;
    } else if (idx < 2 * N_NODES + 256 * D) {
        int e = idx - 2 * N_NODES;
        int k = e >> 7;          // 0..255 (A column)
        int j = e & 127;         // output feature
        float s = 0.f;
        if (k < D) {             // x half pairs with W_root
            #pragma unroll
            for (int c = 0; c < N_CONVS; c++) s += Wroot[c * D * D + j * D + k];
        } else {                 // agg half pairs with W_rel
            int kk = k - D;
            #pragma unroll
            for (int c = 0; c < N_CONVS; c++) s += Wrel[c * D * D + j * D + kk];
        }
        g_B[e] = s;
    } else if (idx < 2 * N_NODES + 256 * D + D) {
        int j = idx - (2 * N_NODES + 256 * D);
        float s = 0.f;
        #pragma unroll
        for (int c = 0; c < N_CONVS; c++) s += brel[c * D + j];
        g_br[j] = s;
    } else if (idx < INIT_TOTAL) {
        int j = idx - (2 * N_NODES + 256 * D + D);
        if (j < D) g_bnsum[j] = 0.f; else g_bnsq[j - D] = 0.f;
    }
}

// ---------------- K1: degree count -------------------------------------------
__global__ void k_count(const int* __restrict__ dst) {
    int i = blockIdx.x * blockDim.x + threadIdx.x;
    if (i < N_EDGES) atomicAdd(&g_cnt[dst[i]], 1);
}

// ---------------- K2: exclusive scan (single CTA, 1024 threads) --------------
__global__ void k_scan() {
    __shared__ int sums[1024];
    const int t = threadIdx.x;
    const int C = 49;                       // 1024*49 = 50176 >= 50000
    int base = t * C;
    int local = 0;
    for (int i = 0; i < C; i++) {
        int idx = base + i;
        if (idx < N_NODES) local += g_cnt[idx];
    }
    sums[t] = local;
    __syncthreads();
    for (int d = 1; d < 1024; d <<= 1) {    // Hillis-Steele inclusive scan
        int v = (t >= d) ? sums[t - d] : 0;
        __syncthreads();
        sums[t] += v;
        __syncthreads();
    }
    int run = (t == 0) ? 0 : sums[t - 1];   // exclusive prefix for this chunk
    for (int i = 0; i < C; i++) {
        int idx = base + i;
        if (idx < N_NODES) { g_off[idx] = run; run += g_cnt[idx]; }
    }
    if (t == 1023) g_off[N_NODES] = sums[1023];
}

// ---------------- K3: scatter edges into CSR ---------------------------------
__global__ void k_scatter(const int* __restrict__ src, const int* __restrict__ dst) {
    int i = blockIdx.x * blockDim.x + threadIdx.x;
    if (i < N_EDGES) {
        int d = dst[i];
        int p = g_off[d] + atomicAdd(&g_cur[d], 1);
        g_ssrc[p] = src[i];
    }
}

// ---------------- K4: aggregate (one warp per node, no atomics) --------------
__global__ void k_agg(const float* __restrict__ x) {
    int warp = (blockIdx.x * blockDim.x + threadIdx.x) >> 5;
    int lane = threadIdx.x & 31;
    if (warp >= N_NODES) return;
    int e0 = g_off[warp], e1 = g_off[warp + 1];
    float4 acc = make_float4(0.f, 0.f, 0.f, 0.f);
    for (int b = e0; b < e1; b += 32) {
        int cnt = min(32, e1 - b);
        int s = (lane < cnt) ? g_ssrc[b + lane] : 0;
        for (int j = 0; j < cnt; j++) {
            int sj = __shfl_sync(0xffffffffu, s, j);
            float4 v = *(const float4*)(x + (size_t)sj * D + lane * 4);
            acc.x += v.x; acc.y += v.y; acc.z += v.z; acc.w += v.w;
        }
    }
    *(float4*)(g_agg + (size_t)warp * D + lane * 4) = acc;
}

// ---------------- K5: fused GEMM  h = [x|agg] @ B + br  ----------------------
// BM=128 rows, BN=128 cols, BK=16, 256 threads, 8x8 microtile per thread.
// fma.rn.f32x2: accumulators paired along N; B pairs come free from SMEM
// ulonglong2 reinterprets; A is duplicated into both halves via mov.b64 pack.
#define BM 128
#define BK 16
#define AS_STRIDE 132

__global__ __launch_bounds__(256, 2) void k_gemm(const float* __restrict__ x) {
    __shared__ __align__(16) float Bs[2][BK * D];         // 16 KB
    __shared__ __align__(16) float As[2][BK * AS_STRIDE]; // ~17 KB, transposed [k][m]

    const int tid = threadIdx.x;
    const int m0 = blockIdx.x * BM;

    const int lm  = tid >> 2;   // 0..63
    const int lf4 = tid & 3;    // 0..3

    auto ldA = [&](int kt, int p, float4& v) {
        int m = lm + p * 64;
        int r = m0 + m;
        int kcol = kt * BK + lf4 * 4;
        if (r < N_NODES) {
            const float* src = (kcol < D) ? (x + (size_t)r * D + kcol)
                                          : (g_agg + (size_t)r * D + (kcol - D));
            v = *(const float4*)src;
        } else {
            v = make_float4(0.f, 0.f, 0.f, 0.f);
        }
    };
    auto stA = [&](int buf, int p, float4 v) {
        int m = lm + p * 64;
        float* d = &As[buf][(lf4 * 4) * AS_STRIDE + m];
        d[0] = v.x; d[AS_STRIDE] = v.y; d[2 * AS_STRIDE] = v.z; d[3 * AS_STRIDE] = v.w;
    };
    auto ldB = [&](int kt, float4& v0, float4& v1) {
        const float4* s = (const float4*)(g_B + kt * BK * D);
        v0 = s[tid]; v1 = s[tid + 256];
    };
    auto stB = [&](int buf, float4 v0, float4 v1) {
        float4* d = (float4*)Bs[buf];
        d[tid] = v0; d[tid + 256] = v1;
    };

    { // prologue: tile 0
        float4 a0, a1, b0, b1;
        ldA(0, 0, a0); ldA(0, 1, a1); ldB(0, b0, b1);
        stA(0, 0, a0); stA(0, 1, a1); stB(0, b0, b1);
    }
    __syncthreads();

    const int ty = tid >> 4, tx = tid & 15;
    u64 acc[8][4];
    #pragma unroll
    for (int i = 0; i < 8; i++)
        #pragma unroll
        for (int p = 0; p < 4; p++) acc[i][p] = 0ull;

    #pragma unroll 1
    for (int kt = 0; kt < 16; kt++) {
        const int buf = kt & 1;
        float4 pa0, pa1, pb0, pb1;
        if (kt < 15) { ldA(kt + 1, 0, pa0); ldA(kt + 1, 1, pa1); ldB(kt + 1, pb0, pb1); }

        const float* Asb = As[buf];
        const float* Bsb = Bs[buf];
        #pragma unroll
        for (int kk = 0; kk < BK; kk++) {
            float4 a0 = *(const float4*)(Asb + kk * AS_STRIDE + ty * 8);
            float4 a1 = *(const float4*)(Asb + kk * AS_STRIDE + ty * 8 + 4);
            ulonglong2 b01 = *(const ulonglong2*)(Bsb + kk * D + tx * 8);
            ulonglong2 b23 = *(const ulonglong2*)(Bsb + kk * D + tx * 8 + 4);
            u64 bp[4] = {b01.x, b01.y, b23.x, b23.y};
            float av[8] = {a0.x, a0.y, a0.z, a0.w, a1.x, a1.y, a1.z, a1.w};
            #pragma unroll
            for (int i = 0; i < 8; i++) {
                u64 ad;
                asm("mov.b64 %0, {%1, %1};" : "=l"(ad) : "f"(av[i]));
                #pragma unroll
                for (int p = 0; p < 4; p++)
                    asm("fma.rn.f32x2 %0, %1, %2, %0;"
                        : "+l"(acc[i][p]) : "l"(ad), "l"(bp[p]));
            }
        }
        if (kt < 15) {
            int nb = (kt + 1) & 1;
            stA(nb, 0, pa0); stA(nb, 1, pa1); stB(nb, pb0, pb1);
        }
        __syncthreads();
    }

    float4 br0 = *(const float4*)(g_br + tx * 8);
    float4 br1 = *(const float4*)(g_br + tx * 8 + 4);
    float brv[8] = {br0.x, br0.y, br0.z, br0.w, br1.x, br1.y, br1.z, br1.w};
    #pragma unroll
    for (int i = 0; i < 8; i++) {
        int r = m0 + ty * 8 + i;
        if (r >= N_NODES) continue;
        float o[8];
        #pragma unroll
        for (int p = 0; p < 4; p++) {
            float lo, hi;
            asm("mov.b64 {%0, %1}, %2;" : "=f"(lo), "=f"(hi) : "l"(acc[i][p]));
            o[2 * p]     = lo + brv[2 * p];
            o[2 * p + 1] = hi + brv[2 * p + 1];
        }
        float4* dst = (float4*)(g_h + (size_t)r * D + tx * 8);
        dst[0] = make_float4(o[0], o[1], o[2], o[3]);
        dst[1] = make_float4(o[4], o[5], o[6], o[7]);
    }
}

// ---------------- K6: BN statistics (sum / sumsq per feature) ----------------
__global__ void k_stats() {
    int f = threadIdx.x;               // 128 threads
    float s = 0.f, q = 0.f;
    for (int r = blockIdx.x; r < N_NODES; r += gridDim.x) {
        float v = g_h[(size_t)r * D + f];
        s += v; q += v * v;
    }
    atomicAdd(&g_bnsum[f], s);
    atomicAdd(&g_bnsq[f], q);
}

// ---------------- K6b: finalize scale/shift ----------------------------------
__global__ void k_fin(const float* __restrict__ gamma, const float* __restrict__ beta) {
    int f = threadIdx.x;
    float mean = g_bnsum[f] * (1.f / N_NODES);
    float var  = g_bnsq[f] * (1.f / N_NODES) - mean * mean;
    float sc   = gamma[f] * rsqrtf(var + EPS);
    g_scale[f] = sc;
    g_shift[f] = beta[f] - mean * sc;
}

// ---------------- K7: per-graph max & min of RAW h (batch is sorted) ---------
__global__ void k_pool(const int* __restrict__ batch) {
    const int g = blockIdx.x;
    const int f = threadIdx.x;
    // lower_bound(batch, g) and lower_bound(batch, g+1)
    int lo = 0, hi = N_NODES;
    while (lo < hi) { int mid = (lo + hi) >> 1; if (batch[mid] < g) lo = mid + 1; else hi = mid; }
    int start = lo;
    hi = N_NODES;
    while (lo < hi) { int mid = (lo + hi) >> 1; if (batch[mid] < g + 1) lo = mid + 1; else hi = mid; }
    int end = lo;

    const float NEG_INF = __int_as_float(0xff800000);
    float mx = NEG_INF, mn = -NEG_INF;
    for (int n = start; n < end; n++) {
        float v = g_h[(size_t)n * D + f];
        mx = fmaxf(mx, v); mn = fminf(mn, v);
    }
    g_pmax[g * D + f] = mx;
    g_pmin[g * D + f] = mn;
}

// ---------------- K8: affine(BN) + relu on pooled, then classifier -----------
__global__ void k_cls(const float* __restrict__ Wc, const float* __restrict__ bc,
                      float* __restrict__ out) {
    __shared__ float ps[D];
    const int g = blockIdx.x;
    const int f = threadIdx.x;       // 128 threads
    const float NEG_INF = __int_as_float(0xff800000);

    float mx = g_pmax[g * D + f];
    float v;
    if (mx == NEG_INF) {
        v = 0.f;                     // empty segment: relu(-inf) = 0
    } else {
        float sc = g_scale[f], sh = g_shift[f];
        float t = (sc >= 0.f) ? mx : g_pmin[g * D + f];  // max-pool commutes with monotone affine
        v = fmaxf(fmaf(sc, t, sh), 0.f);
    }
    ps[f] = v;
    __syncthreads();

    if (f < 96) {
        float acc = bc[f];
        const float4* w = (const float4*)(Wc + f * D);
        const float4* p = (const float4*)ps;
        #pragma unroll
        for (int k = 0; k < D / 4; k++) {
            float4 wv = w[k], pv = p[k];
            acc += wv.x * pv.x + wv.y * pv.y + wv.z * pv.z + wv.w * pv.w;
        }
        out[g * 96 + f] = acc;
    }
}

// ---------------- launch ------------------------------------------------------
extern "C" void kernel_launch(void* const* d_in, const int* in_sizes, int n_in,
                              void* d_out, int out_size) {
    const float* x     = (const float*)d_in[0];
    const int*   ei    = (const int*)d_in[1];   // [2, N_EDGES]: src then dst
    const int*   batch = (const int*)d_in[2];
    /* d_in[3] = i (unused, i=0 branch) */
    const float* Wrel  = (const float*)d_in[4];
    const float* brel  = (const float*)d_in[5];
    const float* Wroot = (const float*)d_in[6];
    const float* gamma = (const float*)d_in[7];
    const float* beta  = (const float*)d_in[8];
    const float* Wc    = (const float*)d_in[9];
    const float* bc    = (const float*)d_in[10];
    float* out = (float*)d_out;

    const int* src = ei;
    const int* dst = ei + N_EDGES;

    k_init<<<(INIT_TOTAL + 255) / 256, 256>>>(Wrel, brel, Wroot);
    k_count<<<(N_EDGES + 255) / 256, 256>>>(dst);
    k_scan<<<1, 1024>>>();
    k_scatter<<<(N_EDGES + 255) / 256, 256>>>(src, dst);
    k_agg<<<(N_NODES * 32 + 255) / 256, 256>>>(x);
    k_gemm<<<(N_NODES + BM - 1) / BM, 256>>>(x);
    k_stats<<<256, 128>>>();
    k_fin<<<1, 128>>>(gamma, beta);
    k_pool<<<N_GRAPHS, 128>>>(batch);
    k_cls<<<N_GRAPHS, 128>>>(Wc, bc, out);
}

// round 3
// speedup vs baseline: 1.5156x; 1.5156x over previous
#include <cuda_runtime.h>
#include <cuda_fp16.h>
#include <cstdint>

#define N_NODES 50000
#define N_EDGES 800000
#define D 128
#define N_GRAPHS 512
#define N_CONVS 5
#define EPS 1e-5f

typedef unsigned long long u64;

// ---------------- scratch (static device globals; no allocation) -------------
__device__ int    g_cnt[N_NODES];
__device__ int    g_cur[N_NODES];
__device__ int    g_off[N_NODES + 1];
__device__ int    g_ssrc[N_EDGES];
__device__ __half g_x16[(size_t)N_NODES * D];
__device__ float  g_agg[(size_t)N_NODES * D];
__device__ float  g_h[(size_t)N_NODES * D];
__device__ float  g_B[256 * D];     // folded weights, k-major: B[k][j]
__device__ float  g_br[D];          // folded bias
__device__ float  g_bnsum[D];
__device__ float  g_bnsq[D];

// ---------------- K0: init + weight folding + x->fp16 ------------------------
#define FOLD_TOTAL (2 * N_NODES + 256 * D + D + 2 * D)   // 133152
#define X4_TOTAL   ((N_NODES * D) / 4)                   // 1.6M float4 groups
#define INIT_TOTAL (FOLD_TOTAL + X4_TOTAL)
__global__ void k_init(const float* __restrict__ x,
                       const float* __restrict__ Wrel,
                       const float* __restrict__ brel,
                       const float* __restrict__ Wroot) {
    int idx = blockIdx.x * blockDim.x + threadIdx.x;
    if (idx < N_NODES) {
        g_cnt[idx] = 0;
    } else if (idx < 2 * N_NODES) {
        g_cur[idx - N_NODES] = 0;
    } else if (idx < 2 * N_NODES + 256 * D) {
        int e = idx - 2 * N_NODES;
        int k = e >> 7;          // 0..255 (A column)
        int j = e & 127;         // output feature
        float s = 0.f;
        if (k < D) {             // x half pairs with W_root
            #pragma unroll
            for (int c = 0; c < N_CONVS; c++) s += Wroot[c * D * D + j * D + k];
        } else {                 // agg half pairs with W_rel
            int kk = k - D;
            #pragma unroll
            for (int c = 0; c < N_CONVS; c++) s += Wrel[c * D * D + j * D + kk];
        }
        g_B[e] = s;
    } else if (idx < 2 * N_NODES + 256 * D + D) {
        int j = idx - (2 * N_NODES + 256 * D);
        float s = 0.f;
        #pragma unroll
        for (int c = 0; c < N_CONVS; c++) s += brel[c * D + j];
        g_br[j] = s;
    } else if (idx < FOLD_TOTAL) {
        int j = idx - (2 * N_NODES + 256 * D + D);
        if (j < D) g_bnsum[j] = 0.f; else g_bnsq[j - D] = 0.f;
    } else if (idx < INIT_TOTAL) {
        int e4 = idx - FOLD_TOTAL;
        float4 v = ((const float4*)x)[e4];
        __half2* o = (__half2*)g_x16;
        o[e4 * 2]     = __floats2half2_rn(v.x, v.y);
        o[e4 * 2 + 1] = __floats2half2_rn(v.z, v.w);
    }
}

// ---------------- K1: degree count -------------------------------------------
__global__ void k_count(const int* __restrict__ dst) {
    int i = blockIdx.x * blockDim.x + threadIdx.x;
    if (i < N_EDGES) atomicAdd(&g_cnt[dst[i]], 1);
}

// ---------------- K2: exclusive scan (single CTA, coalesced warp chunks) -----
__global__ void k_scan() {
    __shared__ int wsum[32];
    const int t = threadIdx.x;          // 1024 threads = 32 warps
    const int w = t >> 5, lane = t & 31;
    const int CHUNK = 1568;             // 32*1568 = 50176 >= 50000
    const int base = w * CHUNK;

    // phase 1: per-warp total (coalesced, lane-strided)
    int tot = 0;
    for (int i = lane; i < CHUNK; i += 32) {
        int idx = base + i;
        tot += (idx < N_NODES) ? g_cnt[idx] : 0;
    }
    #pragma unroll
    for (int d = 16; d; d >>= 1) tot += __shfl_down_sync(0xffffffffu, tot, d);
    if (lane == 0) wsum[w] = tot;
    __syncthreads();

    if (w == 0) {
        int v = wsum[lane];
        int incl = v;
        #pragma unroll
        for (int d = 1; d < 32; d <<= 1) {
            int u = __shfl_up_sync(0xffffffffu, incl, d);
            if (lane >= d) incl += u;
        }
        wsum[lane] = incl - v;          // exclusive warp base
        if (lane == 31) g_off[N_NODES] = incl;
    }
    __syncthreads();

    // phase 2: scan within chunk (coalesced)
    int run = wsum[w];
    for (int i = lane; i < CHUNK; i += 32) {
        int idx = base + i;
        int v = (idx < N_NODES) ? g_cnt[idx] : 0;
        int incl = v;
        #pragma unroll
        for (int d = 1; d < 32; d <<= 1) {
            int u = __shfl_up_sync(0xffffffffu, incl, d);
            if (lane >= d) incl += u;
        }
        if (idx < N_NODES) g_off[idx] = run + incl - v;
        run += __shfl_sync(0xffffffffu, incl, 31);
    }
}

// ---------------- K3: scatter edges into CSR ---------------------------------
__global__ void k_scatter(const int* __restrict__ src, const int* __restrict__ dst) {
    int i = blockIdx.x * blockDim.x + threadIdx.x;
    if (i < N_EDGES) {
        int d = dst[i];
        int p = g_off[d] + atomicAdd(&g_cur[d], 1);
        g_ssrc[p] = src[i];
    }
}

// ---------------- K4: aggregate from fp16 x (one warp per node, no atomics) --
__global__ void k_agg() {
    int warp = (blockIdx.x * blockDim.x + threadIdx.x) >> 5;
    int lane = threadIdx.x & 31;
    if (warp >= N_NODES) return;
    int e0 = g_off[warp], e1 = g_off[warp + 1];
    float4 acc = make_float4(0.f, 0.f, 0.f, 0.f);
    const __half2* xp = (const __half2*)g_x16;
    for (int b = e0; b < e1; b += 32) {
        int cnt = min(32, e1 - b);
        int s = (lane < cnt) ? g_ssrc[b + lane] : 0;
        for (int j = 0; j < cnt; j++) {
            int sj = __shfl_sync(0xffffffffu, s, j);
            // 4 halves per lane: 32 lanes x 8B = 256B per row
            uint2 raw = *(const uint2*)(xp + (size_t)sj * (D / 2) + lane * 2);
            float2 f0 = __half22float2(*(__half2*)&raw.x);
            float2 f1 = __half22float2(*(__half2*)&raw.y);
            acc.x += f0.x; acc.y += f0.y; acc.z += f1.x; acc.w += f1.y;
        }
    }
    *(float4*)(g_agg + (size_t)warp * D + lane * 4) = acc;
}

// ---------------- K5: fused GEMM h=[x|agg]@B+br, + BN stats epilogue ---------
#define BM 128
#define BK 16
#define AS_STRIDE 132

union SmemU {
    struct {
        float Bs[2][BK * D];          // 16 KB
        float As[2][BK * AS_STRIDE];  // ~17 KB
    } mm;
    float red[16][256];               // 16 KB (stats reduction: [ty][col*2+{0,1}])
};

__global__ __launch_bounds__(256, 2) void k_gemm(const float* __restrict__ x) {
    __shared__ __align__(16) SmemU sm;

    const int tid = threadIdx.x;
    const int m0 = blockIdx.x * BM;

    const int lm  = tid >> 2;   // 0..63
    const int lf4 = tid & 3;    // 0..3

    auto ldA = [&](int kt, int p, float4& v) {
        int m = lm + p * 64;
        int r = m0 + m;
        int kcol = kt * BK + lf4 * 4;
        if (r < N_NODES) {
            const float* src = (kcol < D) ? (x + (size_t)r * D + kcol)
                                          : (g_agg + (size_t)r * D + (kcol - D));
            v = *(const float4*)src;
        } else {
            v = make_float4(0.f, 0.f, 0.f, 0.f);
        }
    };
    auto stA = [&](int buf, int p, float4 v) {
        int m = lm + p * 64;
        float* d = &sm.mm.As[buf][(lf4 * 4) * AS_STRIDE + m];
        d[0] = v.x; d[AS_STRIDE] = v.y; d[2 * AS_STRIDE] = v.z; d[3 * AS_STRIDE] = v.w;
    };
    auto ldB = [&](int kt, float4& v0, float4& v1) {
        const float4* s = (const float4*)(g_B + kt * BK * D);
        v0 = s[tid]; v1 = s[tid + 256];
    };
    auto stB = [&](int buf, float4 v0, float4 v1) {
        float4* d = (float4*)sm.mm.Bs[buf];
        d[tid] = v0; d[tid + 256] = v1;
    };

    { // prologue: tile 0
        float4 a0, a1, b0, b1;
        ldA(0, 0, a0); ldA(0, 1, a1); ldB(0, b0, b1);
        stA(0, 0, a0); stA(0, 1, a1); stB(0, b0, b1);
    }
    __syncthreads();

    const int ty = tid >> 4, tx = tid & 15;
    u64 acc[8][4];
    #pragma unroll
    for (int i = 0; i < 8; i++)
        #pragma unroll
        for (int p = 0; p < 4; p++) acc[i][p] = 0ull;

    #pragma unroll 1
    for (int kt = 0; kt < 16; kt++) {
        const int buf = kt & 1;
        float4 pa0, pa1, pb0, pb1;
        if (kt < 15) { ldA(kt + 1, 0, pa0); ldA(kt + 1, 1, pa1); ldB(kt + 1, pb0, pb1); }

        const float* Asb = sm.mm.As[buf];
        const float* Bsb = sm.mm.Bs[buf];
        #pragma unroll
        for (int kk = 0; kk < BK; kk++) {
            float4 a0 = *(const float4*)(Asb + kk * AS_STRIDE + ty * 8);
            float4 a1 = *(const float4*)(Asb + kk * AS_STRIDE + ty * 8 + 4);
            ulonglong2 b01 = *(const ulonglong2*)(Bsb + kk * D + tx * 8);
            ulonglong2 b23 = *(const ulonglong2*)(Bsb + kk * D + tx * 8 + 4);
            u64 bp[4] = {b01.x, b01.y, b23.x, b23.y};
            float av[8] = {a0.x, a0.y, a0.z, a0.w, a1.x, a1.y, a1.z, a1.w};
            #pragma unroll
            for (int i = 0; i < 8; i++) {
                u64 ad;
                asm("mov.b64 %0, {%1, %1};" : "=l"(ad) : "f"(av[i]));
                #pragma unroll
                for (int p = 0; p < 4; p++)
                    asm("fma.rn.f32x2 %0, %1, %2, %0;"
                        : "+l"(acc[i][p]) : "l"(ad), "l"(bp[p]));
            }
        }
        if (kt < 15) {
            int nb = (kt + 1) & 1;
            stA(nb, 0, pa0); stA(nb, 1, pa1); stB(nb, pb0, pb1);
        }
        __syncthreads();
    }

    // epilogue: bias, store h, accumulate BN stats for this tile
    float4 br0 = *(const float4*)(g_br + tx * 8);
    float4 br1 = *(const float4*)(g_br + tx * 8 + 4);
    float brv[8] = {br0.x, br0.y, br0.z, br0.w, br1.x, br1.y, br1.z, br1.w};
    float s8[8], q8[8];
    #pragma unroll
    for (int p = 0; p < 8; p++) { s8[p] = 0.f; q8[p] = 0.f; }

    #pragma unroll
    for (int i = 0; i < 8; i++) {
        int r = m0 + ty * 8 + i;
        if (r >= N_NODES) continue;
        float o[8];
        #pragma unroll
        for (int p = 0; p < 4; p++) {
            float lo, hi;
            asm("mov.b64 {%0, %1}, %2;" : "=f"(lo), "=f"(hi) : "l"(acc[i][p]));
            o[2 * p]     = lo + brv[2 * p];
            o[2 * p + 1] = hi + brv[2 * p + 1];
        }
        #pragma unroll
        for (int p = 0; p < 8; p++) { s8[p] += o[p]; q8[p] += o[p] * o[p]; }
        float4* dst = (float4*)(g_h + (size_t)r * D + tx * 8);
        dst[0] = make_float4(o[0], o[1], o[2], o[3]);
        dst[1] = make_float4(o[4], o[5], o[6], o[7]);
    }

    __syncthreads();   // As/Bs dead; reuse smem as red[]
    #pragma unroll
    for (int p = 0; p < 8; p++) {
        int col = tx * 8 + p;
        sm.red[ty][((col & 63) << 2) | ((col >> 6) << 1)]     = s8[p];
        sm.red[ty][((col & 63) << 2) | ((col >> 6) << 1) | 1] = q8[p];
    }
    __syncthreads();
    if (tid < D) {
        int col = tid;
        int o = ((col & 63) << 2) | ((col >> 6) << 1);
        float s = 0.f, q = 0.f;
        #pragma unroll
        for (int t = 0; t < 16; t++) { s += sm.red[t][o]; q += sm.red[t][o | 1]; }
        atomicAdd(&g_bnsum[col], s);
        atomicAdd(&g_bnsq[col], q);
    }
}

// ---------------- K6: BN finalize + per-graph pool + relu + classifier -------
__global__ void k_final(const int* __restrict__ batch,
                        const float* __restrict__ gamma, const float* __restrict__ beta,
                        const float* __restrict__ Wc, const float* __restrict__ bc,
                        float* __restrict__ out) {
    __shared__ float ps[D];
    const int g = blockIdx.x;
    const int f = threadIdx.x;       // 128 threads

    float mean = g_bnsum[f] * (1.f / N_NODES);
    float var  = g_bnsq[f] * (1.f / N_NODES) - mean * mean;
    float sc   = gamma[f] * rsqrtf(var + EPS);
    float sh   = beta[f] - mean * sc;

    // lower_bound(batch, g) and lower_bound(batch, g+1); batch is sorted
    int lo = 0, hi = N_NODES;
    while (lo < hi) { int mid = (lo + hi) >> 1; if (batch[mid] < g) lo = mid + 1; else hi = mid; }
    int start = lo;
    hi = N_NODES;
    while (lo < hi) { int mid = (lo + hi) >> 1; if (batch[mid] < g + 1) lo = mid + 1; else hi = mid; }
    int end = lo;

    const float NEG_INF = __int_as_float(0xff800000);
    float mx = NEG_INF, mn = -NEG_INF;
    for (int n = start; n < end; n++) {
        float v = g_h[(size_t)n * D + f];
        mx = fmaxf(mx, v); mn = fminf(mn, v);
    }

    float v;
    if (start == end) {
        v = 0.f;                     // empty segment: relu(-inf) = 0
    } else {
        float t = (sc >= 0.f) ? mx : mn;   // max-pool commutes with monotone affine
        v = fmaxf(fmaf(sc, t, sh), 0.f);
    }
    ps[f] = v;
    __syncthreads();

    if (f < 96) {
        float acc = bc[f];
        const float4* w = (const float4*)(Wc + f * D);
        const float4* p = (const float4*)ps;
        #pragma unroll
        for (int k = 0; k < D / 4; k++) {
            float4 wv = w[k], pv = p[k];
            acc += wv.x * pv.x + wv.y * pv.y + wv.z * pv.z + wv.w * pv.w;
        }
        out[g * 96 + f] = acc;
    }
}

// ---------------- launch ------------------------------------------------------
extern "C" void kernel_launch(void* const* d_in, const int* in_sizes, int n_in,
                              void* d_out, int out_size) {
    const float* x     = (const float*)d_in[0];
    const int*   ei    = (const int*)d_in[1];   // [2, N_EDGES]: src then dst
    const int*   batch = (const int*)d_in[2];
    /* d_in[3] = i (unused, i=0 branch) */
    const float* Wrel  = (const float*)d_in[4];
    const float* brel  = (const float*)d_in[5];
    const float* Wroot = (const float*)d_in[6];
    const float* gamma = (const float*)d_in[7];
    const float* beta  = (const float*)d_in[8];
    const float* Wc    = (const float*)d_in[9];
    const float* bc    = (const float*)d_in[10];
    float* out = (float*)d_out;

    const int* src = ei;
    const int* dst = ei + N_EDGES;

    k_init<<<(INIT_TOTAL + 255) / 256, 256>>>(x, Wrel, brel, Wroot);
    k_count<<<(N_EDGES + 255) / 256, 256>>>(dst);
    k_scan<<<1, 1024>>>();
    k_scatter<<<(N_EDGES + 255) / 256, 256>>>(src, dst);
    k_agg<<<(N_NODES * 32 + 255) / 256, 256>>>();
    k_gemm<<<(N_NODES + BM - 1) / BM, 256>>>(x);
    k_final<<<N_GRAPHS, 128>>>(batch, gamma, beta, Wc, bc, out);
}

// round 4
// speedup vs baseline: 1.7302x; 1.1416x over previous
#include <cuda_runtime.h>
#include <cuda_fp16.h>
#include <cstdint>

#define N_NODES 50000
#define N_EDGES 800000
#define D 128
#define N_GRAPHS 512
#define N_CONVS 5
#define EPS 1e-5f

typedef unsigned long long u64;
typedef unsigned int u32;

// ---------------- scratch (static device globals; no allocation) -------------
__device__ int    g_cnt[N_NODES];
__device__ int    g_cur[N_NODES];
__device__ int    g_off[N_NODES + 1];
__device__ int    g_ssrc[N_EDGES];
__device__ __half g_x16[(size_t)N_NODES * D];
__device__ __half g_agg16[(size_t)N_NODES * D];
__device__ float  g_h[(size_t)N_NODES * D];
__device__ __half g_B16[256 * D];   // folded weights, k-major: B[k][j], fp16
__device__ float  g_br[D];          // folded bias (fp32)
__device__ float  g_bnsum[D];
__device__ float  g_bnsq[D];

// ---------------- K0: init + weight folding + x->fp16 ------------------------
#define FOLD_TOTAL (2 * N_NODES + 256 * D + D + 2 * D)   // 133152
#define X4_TOTAL   ((N_NODES * D) / 4)                   // 1.6M float4 groups
#define INIT_TOTAL (FOLD_TOTAL + X4_TOTAL)
__global__ void k_init(const float* __restrict__ x,
                       const float* __restrict__ Wrel,
                       const float* __restrict__ brel,
                       const float* __restrict__ Wroot) {
    int idx = blockIdx.x * blockDim.x + threadIdx.x;
    if (idx < N_NODES) {
        g_cnt[idx] = 0;
    } else if (idx < 2 * N_NODES) {
        g_cur[idx - N_NODES] = 0;
    } else if (idx < 2 * N_NODES + 256 * D) {
        int e = idx - 2 * N_NODES;
        int k = e >> 7;          // 0..255 (A column)
        int j = e & 127;         // output feature
        float s = 0.f;
        if (k < D) {             // x half pairs with W_root
            #pragma unroll
            for (int c = 0; c < N_CONVS; c++) s += Wroot[c * D * D + j * D + k];
        } else {                 // agg half pairs with W_rel
            int kk = k - D;
            #pragma unroll
            for (int c = 0; c < N_CONVS; c++) s += Wrel[c * D * D + j * D + kk];
        }
        g_B16[e] = __float2half_rn(s);
    } else if (idx < 2 * N_NODES + 256 * D + D) {
        int j = idx - (2 * N_NODES + 256 * D);
        float s = 0.f;
        #pragma unroll
        for (int c = 0; c < N_CONVS; c++) s += brel[c * D + j];
        g_br[j] = s;
    } else if (idx < FOLD_TOTAL) {
        int j = idx - (2 * N_NODES + 256 * D + D);
        if (j < D) g_bnsum[j] = 0.f; else g_bnsq[j - D] = 0.f;
    } else if (idx < INIT_TOTAL) {
        int e4 = idx - FOLD_TOTAL;
        float4 v = ((const float4*)x)[e4];
        __half2* o = (__half2*)g_x16;
        o[e4 * 2]     = __floats2half2_rn(v.x, v.y);
        o[e4 * 2 + 1] = __floats2half2_rn(v.z, v.w);
    }
}

// ---------------- K1: degree count -------------------------------------------
__global__ void k_count(const int* __restrict__ dst) {
    int i = blockIdx.x * blockDim.x + threadIdx.x;
    if (i < N_EDGES) atomicAdd(&g_cnt[dst[i]], 1);
}

// ---------------- K2: exclusive scan (single CTA, coalesced warp chunks) -----
__global__ void k_scan() {
    __shared__ int wsum[32];
    const int t = threadIdx.x;          // 1024 threads = 32 warps
    const int w = t >> 5, lane = t & 31;
    const int CHUNK = 1568;             // 32*1568 = 50176 >= 50000
    const int base = w * CHUNK;

    int tot = 0;
    for (int i = lane; i < CHUNK; i += 32) {
        int idx = base + i;
        tot += (idx < N_NODES) ? g_cnt[idx] : 0;
    }
    #pragma unroll
    for (int d = 16; d; d >>= 1) tot += __shfl_down_sync(0xffffffffu, tot, d);
    if (lane == 0) wsum[w] = tot;
    __syncthreads();

    if (w == 0) {
        int v = wsum[lane];
        int incl = v;
        #pragma unroll
        for (int d = 1; d < 32; d <<= 1) {
            int u = __shfl_up_sync(0xffffffffu, incl, d);
            if (lane >= d) incl += u;
        }
        wsum[lane] = incl - v;          // exclusive warp base
        if (lane == 31) g_off[N_NODES] = incl;
    }
    __syncthreads();

    int run = wsum[w];
    for (int i = lane; i < CHUNK; i += 32) {
        int idx = base + i;
        int v = (idx < N_NODES) ? g_cnt[idx] : 0;
        int incl = v;
        #pragma unroll
        for (int d = 1; d < 32; d <<= 1) {
            int u = __shfl_up_sync(0xffffffffu, incl, d);
            if (lane >= d) incl += u;
        }
        if (idx < N_NODES) g_off[idx] = run + incl - v;
        run += __shfl_sync(0xffffffffu, incl, 31);
    }
}

// ---------------- K3: scatter edges into CSR ---------------------------------
__global__ void k_scatter(const int* __restrict__ src, const int* __restrict__ dst) {
    int i = blockIdx.x * blockDim.x + threadIdx.x;
    if (i < N_EDGES) {
        int d = dst[i];
        int p = g_off[d] + atomicAdd(&g_cur[d], 1);
        g_ssrc[p] = src[i];
    }
}

// ---------------- K4: aggregate fp16 x -> fp16 agg (warp/node, no atomics) ---
__global__ void k_agg() {
    int warp = (blockIdx.x * blockDim.x + threadIdx.x) >> 5;
    int lane = threadIdx.x & 31;
    if (warp >= N_NODES) return;
    int e0 = g_off[warp], e1 = g_off[warp + 1];
    float4 acc = make_float4(0.f, 0.f, 0.f, 0.f);
    const __half2* xp = (const __half2*)g_x16;
    for (int b = e0; b < e1; b += 32) {
        int cnt = min(32, e1 - b);
        int s = (lane < cnt) ? g_ssrc[b + lane] : 0;
        #pragma unroll 4
        for (int j = 0; j < cnt; j++) {
            int sj = __shfl_sync(0xffffffffu, s, j);
            uint2 raw = *(const uint2*)(xp + (size_t)sj * (D / 2) + lane * 2);
            float2 f0 = __half22float2(*(__half2*)&raw.x);
            float2 f1 = __half22float2(*(__half2*)&raw.y);
            acc.x += f0.x; acc.y += f0.y; acc.z += f1.x; acc.w += f1.y;
        }
    }
    __half2 h0 = __floats2half2_rn(acc.x, acc.y);
    __half2 h1 = __floats2half2_rn(acc.z, acc.w);
    uint2 o;
    o.x = *(u32*)&h0; o.y = *(u32*)&h1;
    *(uint2*)(g_agg16 + (size_t)warp * D + lane * 4) = o;
}

// ---------------- K5: HMMA GEMM  h = [x16|agg16] @ B16 + br, + BN stats ------
// CTA tile 128x128, K=256. 256 thr = 8 warps (4x2), warp tile 32x64.
// B fully resident in smem (256 x 136 halves, +8 pad -> conflict-free ldmatrix).
// A double-buffered (2 x 128 x 72 halves). mma.sync.m16n8k16 f16->f32.
#define BS_ROWPAD 136               // halves per B row (128 + 8)
#define AS_ROWPAD 72                // halves per A row (64 + 8)
#define BS_BYTES  (256 * BS_ROWPAD * 2)          // 69632
#define AS_BYTES  (2 * 128 * AS_ROWPAD * 2)      // 36864
#define GEMM_SMEM (BS_BYTES + AS_BYTES)          // 106496

__device__ __forceinline__ void ldsm4(u32& r0, u32& r1, u32& r2, u32& r3, u32 a) {
    asm volatile("ldmatrix.sync.aligned.m8n8.x4.shared.b16 {%0,%1,%2,%3}, [%4];"
                 : "=r"(r0), "=r"(r1), "=r"(r2), "=r"(r3) : "r"(a));
}
__device__ __forceinline__ void ldsm4t(u32& r0, u32& r1, u32& r2, u32& r3, u32 a) {
    asm volatile("ldmatrix.sync.aligned.m8n8.x4.trans.shared.b16 {%0,%1,%2,%3}, [%4];"
                 : "=r"(r0), "=r"(r1), "=r"(r2), "=r"(r3) : "r"(a));
}
__device__ __forceinline__ void mma16816(float* c, u32 a0, u32 a1, u32 a2, u32 a3,
                                         u32 b0, u32 b1) {
    asm volatile("mma.sync.aligned.m16n8k16.row.col.f32.f16.f16.f32 "
                 "{%0,%1,%2,%3}, {%4,%5,%6,%7}, {%8,%9}, {%0,%1,%2,%3};"
                 : "+f"(c[0]), "+f"(c[1]), "+f"(c[2]), "+f"(c[3])
                 : "r"(a0), "r"(a1), "r"(a2), "r"(a3), "r"(b0), "r"(b1));
}

extern __shared__ char dynsm[];

__global__ __launch_bounds__(256, 2) void k_gemm() {
    __half* Bs = (__half*)dynsm;
    __half* As = (__half*)(dynsm + BS_BYTES);

    const int tid  = threadIdx.x;
    const int lane = tid & 31;
    const int wid  = tid >> 5;
    const int wm   = wid >> 1;      // 0..3
    const int wn   = wid & 1;       // 0..1
    const int m0   = blockIdx.x * 128;

    // ---- load full B (256 x 128 halves) into padded smem ----
    #pragma unroll
    for (int j = 0; j < 16; j++) {
        int i = tid + j * 256;              // 4096 float4 total
        int row = i >> 4, c = i & 15;
        float4 v = *(const float4*)(g_B16 + row * D + c * 8);
        *(float4*)(Bs + row * BS_ROWPAD + c * 8) = v;
    }

    // ---- A stage loader: stage s covers k in [64s, 64s+64) ----
    auto ldA = [&](int s, float4* pa) {
        const __half* src = (s < 2) ? g_x16 : g_agg16;
        int ko = (s < 2) ? s * 64 : (s - 2) * 64;
        #pragma unroll
        for (int j = 0; j < 4; j++) {
            int i = tid + j * 256;          // 1024 float4 total
            int row = i >> 3, c = i & 7;
            int r = m0 + row;
            if (r < N_NODES)
                pa[j] = *(const float4*)(src + (size_t)r * D + ko + c * 8);
            else
                pa[j] = make_float4(0.f, 0.f, 0.f, 0.f);
        }
    };
    auto stA = [&](int buf, const float4* pa) {
        #pragma unroll
        for (int j = 0; j < 4; j++) {
            int i = tid + j * 256;
            int row = i >> 3, c = i & 7;
            *(float4*)(As + buf * 128 * AS_ROWPAD + row * AS_ROWPAD + c * 8) = pa[j];
        }
    };

    {
        float4 pa[4];
        ldA(0, pa);
        stA(0, pa);
    }
    __syncthreads();

    // ---- per-lane ldmatrix addresses ----
    const int m_off = ((lane >> 3) & 1) * 8 + (lane & 7);
    const int k_off = (lane >> 4) * 8;
    const int kb_off = m_off;           // same formula for B k rows
    const int n_off = k_off;            // (lane>>4)*8

    u32 a_base0 = (u32)__cvta_generic_to_shared(
        As + (wm * 32 + m_off) * AS_ROWPAD + k_off);
    u32 b_base = (u32)__cvta_generic_to_shared(
        Bs + kb_off * BS_ROWPAD + wn * 64 + n_off);

    float acc[2][8][4];
    #pragma unroll
    for (int mt = 0; mt < 2; mt++)
        #pragma unroll
        for (int nt = 0; nt < 8; nt++)
            #pragma unroll
            for (int q = 0; q < 4; q++) acc[mt][nt][q] = 0.f;

    #pragma unroll 1
    for (int s = 0; s < 4; s++) {
        float4 pa[4];
        if (s < 3) ldA(s + 1, pa);
        const int buf = s & 1;
        const u32 a_stage = a_base0 + buf * (128 * AS_ROWPAD * 2);

        #pragma unroll
        for (int k16 = 0; k16 < 4; k16++) {
            u32 a[2][4];
            #pragma unroll
            for (int mt = 0; mt < 2; mt++)
                ldsm4(a[mt][0], a[mt][1], a[mt][2], a[mt][3],
                      a_stage + (mt * 16) * (AS_ROWPAD * 2) + k16 * 32);
            const u32 b_k = b_base + (s * 64 + k16 * 16) * (BS_ROWPAD * 2);
            #pragma unroll
            for (int np = 0; np < 4; np++) {
                u32 b0, b1, b2, b3;
                ldsm4t(b0, b1, b2, b3, b_k + np * 32);
                #pragma unroll
                for (int mt = 0; mt < 2; mt++) {
                    mma16816(acc[mt][np * 2],     a[mt][0], a[mt][1], a[mt][2], a[mt][3], b0, b1);
                    mma16816(acc[mt][np * 2 + 1], a[mt][0], a[mt][1], a[mt][2], a[mt][3], b2, b3);
                }
            }
        }
        if (s < 3) {
            stA(buf ^ 1, pa);
            __syncthreads();
        }
    }

    // ---- epilogue: bias, store h (float2), BN partial stats ----
    const int qr = lane >> 2;     // 0..7
    const int qc = lane & 3;      // 0..3
    float s16[16], q16[16];
    #pragma unroll
    for (int t = 0; t < 16; t++) { s16[t] = 0.f; q16[t] = 0.f; }

    #pragma unroll
    for (int nt = 0; nt < 8; nt++) {
        const int col = wn * 64 + nt * 8 + qc * 2;
        const float2 br = *(const float2*)(g_br + col);
        #pragma unroll
        for (int mt = 0; mt < 2; mt++) {
            #pragma unroll
            for (int hh = 0; hh < 2; hh++) {   // c0c1 row, c2c3 row (+8)
                int r = m0 + wm * 32 + mt * 16 + qr + hh * 8;
                if (r >= N_NODES) continue;
                float v0 = acc[mt][nt][hh * 2]     + br.x;
                float v1 = acc[mt][nt][hh * 2 + 1] + br.y;
                *(float2*)(g_h + (size_t)r * D + col) = make_float2(v0, v1);
                s16[nt * 2]     += v0;  q16[nt * 2]     += v0 * v0;
                s16[nt * 2 + 1] += v1;  q16[nt * 2 + 1] += v1 * v1;
            }
        }
    }

    // ---- reduce stats: smem atomics then one global atomic per col ----
    __syncthreads();                 // all reads of As done; reuse as scratch
    float* sm_s = (float*)(dynsm + BS_BYTES);
    float* sm_q = sm_s + D;
    if (tid < D) { sm_s[tid] = 0.f; sm_q[tid] = 0.f; }
    __syncthreads();
    #pragma unroll
    for (int nt = 0; nt < 8; nt++) {
        int col = wn * 64 + nt * 8 + qc * 2;
        atomicAdd(&sm_s[col], s16[nt * 2]);
        atomicAdd(&sm_q[col], q16[nt * 2]);
        atomicAdd(&sm_s[col + 1], s16[nt * 2 + 1]);
        atomicAdd(&sm_q[col + 1], q16[nt * 2 + 1]);
    }
    __syncthreads();
    if (tid < D) {
        atomicAdd(&g_bnsum[tid], sm_s[tid]);
        atomicAdd(&g_bnsq[tid], sm_q[tid]);
    }
}

// ---------------- K6: BN finalize + per-graph pool + relu + classifier -------
__global__ void k_final(const int* __restrict__ batch,
                        const float* __restrict__ gamma, const float* __restrict__ beta,
                        const float* __restrict__ Wc, const float* __restrict__ bc,
                        float* __restrict__ out) {
    __shared__ float ps[D];
    const int g = blockIdx.x;
    const int f = threadIdx.x;       // 128 threads

    float mean = g_bnsum[f] * (1.f / N_NODES);
    float var  = g_bnsq[f] * (1.f / N_NODES) - mean * mean;
    float sc   = gamma[f] * rsqrtf(var + EPS);
    float sh   = beta[f] - mean * sc;

    int lo = 0, hi = N_NODES;
    while (lo < hi) { int mid = (lo + hi) >> 1; if (batch[mid] < g) lo = mid + 1; else hi = mid; }
    int start = lo;
    hi = N_NODES;
    while (lo < hi) { int mid = (lo + hi) >> 1; if (batch[mid] < g + 1) lo = mid + 1; else hi = mid; }
    int end = lo;

    const float NEG_INF = __int_as_float(0xff800000);
    float mx = NEG_INF, mn = -NEG_INF;
    for (int n = start; n < end; n++) {
        float v = g_h[(size_t)n * D + f];
        mx = fmaxf(mx, v); mn = fminf(mn, v);
    }

    float v;
    if (start == end) {
        v = 0.f;                     // empty segment: relu(-inf) = 0
    } else {
        float t = (sc >= 0.f) ? mx : mn;   // max-pool commutes with monotone affine
        v = fmaxf(fmaf(sc, t, sh), 0.f);
    }
    ps[f] = v;
    __syncthreads();

    if (f < 96) {
        float acc = bc[f];
        const float4* w = (const float4*)(Wc + f * D);
        const float4* p = (const float4*)ps;
        #pragma unroll
        for (int k = 0; k < D / 4; k++) {
            float4 wv = w[k], pv = p[k];
            acc += wv.x * pv.x + wv.y * pv.y + wv.z * pv.z + wv.w * pv.w;
        }
        out[g * 96 + f] = acc;
    }
}

// ---------------- launch ------------------------------------------------------
extern "C" void kernel_launch(void* const* d_in, const int* in_sizes, int n_in,
                              void* d_out, int out_size) {
    const float* x     = (const float*)d_in[0];
    const int*   ei    = (const int*)d_in[1];   // [2, N_EDGES]: src then dst
    const int*   batch = (const int*)d_in[2];
    /* d_in[3] = i (unused, i=0 branch) */
    const float* Wrel  = (const float*)d_in[4];
    const float* brel  = (const float*)d_in[5];
    const float* Wroot = (const float*)d_in[6];
    const float* gamma = (const float*)d_in[7];
    const float* beta  = (const float*)d_in[8];
    const float* Wc    = (const float*)d_in[9];
    const float* bc    = (const float*)d_in[10];
    float* out = (float*)d_out;

    const int* src = ei;
    const int* dst = ei + N_EDGES;

    static int smem_set = 0;
    if (!smem_set) {
        cudaFuncSetAttribute(k_gemm, cudaFuncAttributeMaxDynamicSharedMemorySize,
                             GEMM_SMEM);
        smem_set = 1;
    }

    k_init<<<(INIT_TOTAL + 255) / 256, 256>>>(x, Wrel, brel, Wroot);
    k_count<<<(N_EDGES + 255) / 256, 256>>>(dst);
    k_scan<<<1, 1024>>>();
    k_scatter<<<(N_EDGES + 255) / 256, 256>>>(src, dst);
    k_agg<<<(N_NODES * 32 + 255) / 256, 256>>>();
    k_gemm<<<(N_NODES + 127) / 128, 256, GEMM_SMEM>>>();
    k_final<<<N_GRAPHS, 128>>>(batch, gamma, beta, Wc, bc, out);
}

// round 5
// speedup vs baseline: 1.7306x; 1.0002x over previous
#include <cuda_runtime.h>
#include <cuda_fp16.h>
#include <cstdint>

#define N_NODES 50000
#define N_EDGES 800000
#define D 128
#define N_GRAPHS 512
#define N_CONVS 5
#define EPS 1e-5f

typedef unsigned long long u64;
typedef unsigned int u32;

// ---------------- scratch (static device globals; no allocation) -------------
__device__ int    g_cnt[N_NODES];
__device__ int    g_cur[N_NODES];
__device__ int    g_off[N_NODES + 1];
__device__ int    g_ssrc[N_EDGES];
__device__ __half g_x16[(size_t)N_NODES * D];
__device__ __half g_agg16[(size_t)N_NODES * D];
__device__ __half g_h16[(size_t)N_NODES * D];
__device__ __half g_B16[256 * D];   // folded weights, k-major: B[k][j], fp16
__device__ float  g_br[D];          // folded bias (fp32)
__device__ float  g_bnsum[D];
__device__ float  g_bnsq[D];

// ---------------- K0: zero counters + BN stats -------------------------------
#define ZTOTAL (2 * N_NODES + 2 * D)
__global__ void k_zero() {
    int idx = blockIdx.x * blockDim.x + threadIdx.x;
    if (idx < N_NODES) g_cnt[idx] = 0;
    else if (idx < 2 * N_NODES) g_cur[idx - N_NODES] = 0;
    else if (idx < 2 * N_NODES + D) g_bnsum[idx - 2 * N_NODES] = 0.f;
    else if (idx < ZTOTAL) g_bnsq[idx - 2 * N_NODES - D] = 0.f;
}

// ---------------- K1: degree count (4 edges/thread) + weight fold + x->fp16 --
// The count part is atomic-latency-bound; folding the streaming convert work
// into the same kernel fills its idle issue slots.
#define CNT4      (N_EDGES / 4)                  // 200000
#define BFOLD     (256 * D)                      // 32768
#define X4_TOTAL  ((N_NODES * D) / 4)            // 1600000
#define FC_TOTAL  (CNT4 + BFOLD + D + X4_TOTAL)  // 1832896
__global__ void k_count_fold(const int* __restrict__ dst,
                             const float* __restrict__ x,
                             const float* __restrict__ Wrel,
                             const float* __restrict__ brel,
                             const float* __restrict__ Wroot) {
    int idx = blockIdx.x * blockDim.x + threadIdx.x;
    if (idx < CNT4) {
        int4 d = *(const int4*)(dst + idx * 4);
        atomicAdd(&g_cnt[d.x], 1);
        atomicAdd(&g_cnt[d.y], 1);
        atomicAdd(&g_cnt[d.z], 1);
        atomicAdd(&g_cnt[d.w], 1);
    } else if (idx < CNT4 + BFOLD) {
        int e = idx - CNT4;
        int k = e >> 7;          // 0..255 (A column)
        int j = e & 127;         // output feature
        float s = 0.f;
        if (k < D) {             // x half pairs with W_root
            #pragma unroll
            for (int c = 0; c < N_CONVS; c++) s += Wroot[c * D * D + j * D + k];
        } else {                 // agg half pairs with W_rel
            int kk = k - D;
            #pragma unroll
            for (int c = 0; c < N_CONVS; c++) s += Wrel[c * D * D + j * D + kk];
        }
        g_B16[e] = __float2half_rn(s);
    } else if (idx < CNT4 + BFOLD + D) {
        int j = idx - (CNT4 + BFOLD);
        float s = 0.f;
        #pragma unroll
        for (int c = 0; c < N_CONVS; c++) s += brel[c * D + j];
        g_br[j] = s;
    } else if (idx < FC_TOTAL) {
        int e4 = idx - (CNT4 + BFOLD + D);
        float4 v = ((const float4*)x)[e4];
        __half2* o = (__half2*)g_x16;
        o[e4 * 2]     = __floats2half2_rn(v.x, v.y);
        o[e4 * 2 + 1] = __floats2half2_rn(v.z, v.w);
    }
}

// ---------------- K2: exclusive scan (single CTA, coalesced warp chunks) -----
__global__ void k_scan() {
    __shared__ int wsum[32];
    const int t = threadIdx.x;          // 1024 threads = 32 warps
    const int w = t >> 5, lane = t & 31;
    const int CHUNK = 1568;             // 32*1568 = 50176 >= 50000
    const int base = w * CHUNK;

    int tot = 0;
    for (int i = lane; i < CHUNK; i += 32) {
        int idx = base + i;
        tot += (idx < N_NODES) ? g_cnt[idx] : 0;
    }
    #pragma unroll
    for (int d = 16; d; d >>= 1) tot += __shfl_down_sync(0xffffffffu, tot, d);
    if (lane == 0) wsum[w] = tot;
    __syncthreads();

    if (w == 0) {
        int v = wsum[lane];
        int incl = v;
        #pragma unroll
        for (int d = 1; d < 32; d <<= 1) {
            int u = __shfl_up_sync(0xffffffffu, incl, d);
            if (lane >= d) incl += u;
        }
        wsum[lane] = incl - v;          // exclusive warp base
        if (lane == 31) g_off[N_NODES] = incl;
    }
    __syncthreads();

    int run = wsum[w];
    for (int i = lane; i < CHUNK; i += 32) {
        int idx = base + i;
        int v = (idx < N_NODES) ? g_cnt[idx] : 0;
        int incl = v;
        #pragma unroll
        for (int d = 1; d < 32; d <<= 1) {
            int u = __shfl_up_sync(0xffffffffu, incl, d);
            if (lane >= d) incl += u;
        }
        if (idx < N_NODES) g_off[idx] = run + incl - v;
        run += __shfl_sync(0xffffffffu, incl, 31);
    }
}

// ---------------- K3: scatter edges into CSR (4 edges/thread) ----------------
__global__ void k_scatter(const int* __restrict__ src, const int* __restrict__ dst) {
    int idx = blockIdx.x * blockDim.x + threadIdx.x;
    if (idx < CNT4) {
        int4 d = *(const int4*)(dst + idx * 4);
        int4 s = *(const int4*)(src + idx * 4);
        int p;
        p = g_off[d.x] + atomicAdd(&g_cur[d.x], 1); g_ssrc[p] = s.x;
        p = g_off[d.y] + atomicAdd(&g_cur[d.y], 1); g_ssrc[p] = s.y;
        p = g_off[d.z] + atomicAdd(&g_cur[d.z], 1); g_ssrc[p] = s.z;
        p = g_off[d.w] + atomicAdd(&g_cur[d.w], 1); g_ssrc[p] = s.w;
    }
}

// ---------------- K4: aggregate (half-warp per node, uint4 loads, fp16 out) --
__global__ void k_agg() {
    const int node = (blockIdx.x * blockDim.x + threadIdx.x) >> 4;
    const int hl   = threadIdx.x & 15;
    const u32 hmask = 0xFFFFu << (threadIdx.x & 16);
    if (node >= N_NODES) return;
    const int e0 = g_off[node], e1 = g_off[node + 1];

    float acc[8];
    #pragma unroll
    for (int q = 0; q < 8; q++) acc[q] = 0.f;

    for (int b = e0; b < e1; b += 16) {
        const int cnt = min(16, e1 - b);
        int s = (hl < cnt) ? g_ssrc[b + hl] : 0;
        #pragma unroll 4
        for (int j = 0; j < cnt; j++) {
            int sj = __shfl_sync(hmask, s, j, 16);
            uint4 raw = *(const uint4*)(g_x16 + (size_t)sj * D + hl * 8);
            const __half2* hp = (const __half2*)&raw;
            #pragma unroll
            for (int q = 0; q < 4; q++) {
                float2 f = __half22float2(hp[q]);
                acc[q * 2]     += f.x;
                acc[q * 2 + 1] += f.y;
            }
        }
    }
    uint4 o;
    __half2 h0 = __floats2half2_rn(acc[0], acc[1]);
    __half2 h1 = __floats2half2_rn(acc[2], acc[3]);
    __half2 h2 = __floats2half2_rn(acc[4], acc[5]);
    __half2 h3 = __floats2half2_rn(acc[6], acc[7]);
    o.x = *(u32*)&h0; o.y = *(u32*)&h1; o.z = *(u32*)&h2; o.w = *(u32*)&h3;
    *(uint4*)(g_agg16 + (size_t)node * D + hl * 8) = o;
}

// ---------------- K5: HMMA GEMM  h16 = [x16|agg16] @ B16 + br, + BN stats ----
#define BS_ROWPAD 136               // halves per B row (128 + 8)
#define AS_ROWPAD 72                // halves per A row (64 + 8)
#define BS_BYTES  (256 * BS_ROWPAD * 2)          // 69632
#define AS_BYTES  (2 * 128 * AS_ROWPAD * 2)      // 36864
#define GEMM_SMEM (BS_BYTES + AS_BYTES)          // 106496

__device__ __forceinline__ void ldsm4(u32& r0, u32& r1, u32& r2, u32& r3, u32 a) {
    asm volatile("ldmatrix.sync.aligned.m8n8.x4.shared.b16 {%0,%1,%2,%3}, [%4];"
                 : "=r"(r0), "=r"(r1), "=r"(r2), "=r"(r3) : "r"(a));
}
__device__ __forceinline__ void ldsm4t(u32& r0, u32& r1, u32& r2, u32& r3, u32 a) {
    asm volatile("ldmatrix.sync.aligned.m8n8.x4.trans.shared.b16 {%0,%1,%2,%3}, [%4];"
                 : "=r"(r0), "=r"(r1), "=r"(r2), "=r"(r3) : "r"(a));
}
__device__ __forceinline__ void mma16816(float* c, u32 a0, u32 a1, u32 a2, u32 a3,
                                         u32 b0, u32 b1) {
    asm volatile("mma.sync.aligned.m16n8k16.row.col.f32.f16.f16.f32 "
                 "{%0,%1,%2,%3}, {%4,%5,%6,%7}, {%8,%9}, {%0,%1,%2,%3};"
                 : "+f"(c[0]), "+f"(c[1]), "+f"(c[2]), "+f"(c[3])
                 : "r"(a0), "r"(a1), "r"(a2), "r"(a3), "r"(b0), "r"(b1));
}

extern __shared__ char dynsm[];

__global__ __launch_bounds__(256, 2) void k_gemm() {
    __half* Bs = (__half*)dynsm;
    __half* As = (__half*)(dynsm + BS_BYTES);

    const int tid  = threadIdx.x;
    const int lane = tid & 31;
    const int wid  = tid >> 5;
    const int wm   = wid >> 1;      // 0..3
    const int wn   = wid & 1;       // 0..1
    const int m0   = blockIdx.x * 128;

    // ---- load full B (256 x 128 halves) into padded smem ----
    #pragma unroll
    for (int j = 0; j < 16; j++) {
        int i = tid + j * 256;              // 4096 float4 total
        int row = i >> 4, c = i & 15;
        float4 v = *(const float4*)(g_B16 + row * D + c * 8);
        *(float4*)(Bs + row * BS_ROWPAD + c * 8) = v;
    }

    // ---- A stage loader: stage s covers k in [64s, 64s+64) ----
    auto ldA = [&](int s, float4* pa) {
        const __half* src = (s < 2) ? g_x16 : g_agg16;
        int ko = (s < 2) ? s * 64 : (s - 2) * 64;
        #pragma unroll
        for (int j = 0; j < 4; j++) {
            int i = tid + j * 256;          // 1024 float4 total
            int row = i >> 3, c = i & 7;
            int r = m0 + row;
            if (r < N_NODES)
                pa[j] = *(const float4*)(src + (size_t)r * D + ko + c * 8);
            else
                pa[j] = make_float4(0.f, 0.f, 0.f, 0.f);
        }
    };
    auto stA = [&](int buf, const float4* pa) {
        #pragma unroll
        for (int j = 0; j < 4; j++) {
            int i = tid + j * 256;
            int row = i >> 3, c = i & 7;
            *(float4*)(As + buf * 128 * AS_ROWPAD + row * AS_ROWPAD + c * 8) = pa[j];
        }
    };

    {
        float4 pa[4];
        ldA(0, pa);
        stA(0, pa);
    }
    __syncthreads();

    // ---- per-lane ldmatrix addresses ----
    const int m_off = ((lane >> 3) & 1) * 8 + (lane & 7);
    const int k_off = (lane >> 4) * 8;
    const int kb_off = m_off;
    const int n_off = k_off;

    u32 a_base0 = (u32)__cvta_generic_to_shared(
        As + (wm * 32 + m_off) * AS_ROWPAD + k_off);
    u32 b_base = (u32)__cvta_generic_to_shared(
        Bs + kb_off * BS_ROWPAD + wn * 64 + n_off);

    float acc[2][8][4];
    #pragma unroll
    for (int mt = 0; mt < 2; mt++)
        #pragma unroll
        for (int nt = 0; nt < 8; nt++)
            #pragma unroll
            for (int q = 0; q < 4; q++) acc[mt][nt][q] = 0.f;

    #pragma unroll 1
    for (int s = 0; s < 4; s++) {
        float4 pa[4];
        if (s < 3) ldA(s + 1, pa);
        const int buf = s & 1;
        const u32 a_stage = a_base0 + buf * (128 * AS_ROWPAD * 2);

        #pragma unroll
        for (int k16 = 0; k16 < 4; k16++) {
            u32 a[2][4];
            #pragma unroll
            for (int mt = 0; mt < 2; mt++)
                ldsm4(a[mt][0], a[mt][1], a[mt][2], a[mt][3],
                      a_stage + (mt * 16) * (AS_ROWPAD * 2) + k16 * 32);
            const u32 b_k = b_base + (s * 64 + k16 * 16) * (BS_ROWPAD * 2);
            #pragma unroll
            for (int np = 0; np < 4; np++) {
                u32 b0, b1, b2, b3;
                ldsm4t(b0, b1, b2, b3, b_k + np * 32);
                #pragma unroll
                for (int mt = 0; mt < 2; mt++) {
                    mma16816(acc[mt][np * 2],     a[mt][0], a[mt][1], a[mt][2], a[mt][3], b0, b1);
                    mma16816(acc[mt][np * 2 + 1], a[mt][0], a[mt][1], a[mt][2], a[mt][3], b2, b3);
                }
            }
        }
        if (s < 3) {
            stA(buf ^ 1, pa);
            __syncthreads();
        }
    }

    // ---- epilogue: bias, store h16, BN partial stats (fp32, pre-rounding) ---
    const int qr = lane >> 2;     // 0..7
    const int qc = lane & 3;      // 0..3
    float s16[16], q16[16];
    #pragma unroll
    for (int t = 0; t < 16; t++) { s16[t] = 0.f; q16[t] = 0.f; }

    #pragma unroll
    for (int nt = 0; nt < 8; nt++) {
        const int col = wn * 64 + nt * 8 + qc * 2;
        const float2 br = *(const float2*)(g_br + col);
        #pragma unroll
        for (int mt = 0; mt < 2; mt++) {
            #pragma unroll
            for (int hh = 0; hh < 2; hh++) {   // c0c1 row, c2c3 row (+8)
                int r = m0 + wm * 32 + mt * 16 + qr + hh * 8;
                if (r >= N_NODES) continue;
                float v0 = acc[mt][nt][hh * 2]     + br.x;
                float v1 = acc[mt][nt][hh * 2 + 1] + br.y;
                *(__half2*)(g_h16 + (size_t)r * D + col) = __floats2half2_rn(v0, v1);
                s16[nt * 2]     += v0;  q16[nt * 2]     += v0 * v0;
                s16[nt * 2 + 1] += v1;  q16[nt * 2 + 1] += v1 * v1;
            }
        }
    }

    // ---- reduce stats: smem atomics then one global atomic per col ----
    __syncthreads();                 // all reads of As done; reuse as scratch
    float* sm_s = (float*)(dynsm + BS_BYTES);
    float* sm_q = sm_s + D;
    if (tid < D) { sm_s[tid] = 0.f; sm_q[tid] = 0.f; }
    __syncthreads();
    #pragma unroll
    for (int nt = 0; nt < 8; nt++) {
        int col = wn * 64 + nt * 8 + qc * 2;
        atomicAdd(&sm_s[col], s16[nt * 2]);
        atomicAdd(&sm_q[col], q16[nt * 2]);
        atomicAdd(&sm_s[col + 1], s16[nt * 2 + 1]);
        atomicAdd(&sm_q[col + 1], q16[nt * 2 + 1]);
    }
    __syncthreads();
    if (tid < D) {
        atomicAdd(&g_bnsum[tid], sm_s[tid]);
        atomicAdd(&g_bnsq[tid], sm_q[tid]);
    }
}

// ---------------- K6: BN finalize + per-graph pool + relu + classifier -------
__global__ void k_final(const int* __restrict__ batch,
                        const float* __restrict__ gamma, const float* __restrict__ beta,
                        const float* __restrict__ Wc, const float* __restrict__ bc,
                        float* __restrict__ out) {
    __shared__ float ps[D];
    const int g = blockIdx.x;
    const int f = threadIdx.x;       // 128 threads

    float mean = g_bnsum[f] * (1.f / N_NODES);
    float var  = g_bnsq[f] * (1.f / N_NODES) - mean * mean;
    float sc   = gamma[f] * rsqrtf(var + EPS);
    float sh   = beta[f] - mean * sc;

    int lo = 0, hi = N_NODES;
    while (lo < hi) { int mid = (lo + hi) >> 1; if (batch[mid] < g) lo = mid + 1; else hi = mid; }
    int start = lo;
    hi = N_NODES;
    while (lo < hi) { int mid = (lo + hi) >> 1; if (batch[mid] < g + 1) lo = mid + 1; else hi = mid; }
    int end = lo;

    const float NEG_INF = __int_as_float(0xff800000);
    float mx = NEG_INF, mn = -NEG_INF;
    for (int n = start; n < end; n++) {
        float v = __half2float(g_h16[(size_t)n * D + f]);
        mx = fmaxf(mx, v); mn = fminf(mn, v);
    }

    float v;
    if (start == end) {
        v = 0.f;                     // empty segment: relu(-inf) = 0
    } else {
        float t = (sc >= 0.f) ? mx : mn;   // max-pool commutes with monotone affine
        v = fmaxf(fmaf(sc, t, sh), 0.f);
    }
    ps[f] = v;
    __syncthreads();

    if (f < 96) {
        float acc = bc[f];
        const float4* w = (const float4*)(Wc + f * D);
        const float4* p = (const float4*)ps;
        #pragma unroll
        for (int k = 0; k < D / 4; k++) {
            float4 wv = w[k], pv = p[k];
            acc += wv.x * pv.x + wv.y * pv.y + wv.z * pv.z + wv.w * pv.w;
        }
        out[g * 96 + f] = acc;
    }
}

// ---------------- launch ------------------------------------------------------
extern "C" void kernel_launch(void* const* d_in, const int* in_sizes, int n_in,
                              void* d_out, int out_size) {
    const float* x     = (const float*)d_in[0];
    const int*   ei    = (const int*)d_in[1];   // [2, N_EDGES]: src then dst
    const int*   batch = (const int*)d_in[2];
    /* d_in[3] = i (unused, i=0 branch) */
    const float* Wrel  = (const float*)d_in[4];
    const float* brel  = (const float*)d_in[5];
    const float* Wroot = (const float*)d_in[6];
    const float* gamma = (const float*)d_in[7];
    const float* beta  = (const float*)d_in[8];
    const float* Wc    = (const float*)d_in[9];
    const float* bc    = (const float*)d_in[10];
    float* out = (float*)d_out;

    const int* src = ei;
    const int* dst = ei + N_EDGES;

    static int smem_set = 0;
    if (!smem_set) {
        cudaFuncSetAttribute(k_gemm, cudaFuncAttributeMaxDynamicSharedMemorySize,
                             GEMM_SMEM);
        smem_set = 1;
    }

    k_zero<<<(ZTOTAL + 255) / 256, 256>>>();
    k_count_fold<<<(FC_TOTAL + 255) / 256, 256>>>(dst, x, Wrel, brel, Wroot);
    k_scan<<<1, 1024>>>();
    k_scatter<<<(CNT4 + 255) / 256, 256>>>(src, dst);
    k_agg<<<(N_NODES * 16 + 255) / 256, 256>>>();
    k_gemm<<<(N_NODES + 127) / 128, 256, GEMM_SMEM>>>();
    k_final<<<N_GRAPHS, 128>>>(batch, gamma, beta, Wc, bc, out);
}

// round 6
// speedup vs baseline: 1.7742x; 1.0252x over previous
#include <cuda_runtime.h>
#include <cuda_fp16.h>
#include <cstdint>

#define N_NODES 50000
#define N_EDGES 800000
#define D 128
#define N_GRAPHS 512
#define N_CONVS 5
#define EPS 1e-5f

typedef unsigned long long u64;
typedef unsigned int u32;

// ---------------- scratch (static device globals; no allocation) -------------
__device__ int    g_cnt[N_NODES];
__device__ int    g_cur[N_NODES];
__device__ int    g_off[N_NODES + 1];
__device__ int    g_ssrc[N_EDGES];
__device__ __half g_x16[(size_t)N_NODES * D];
__device__ __half g_agg16[(size_t)N_NODES * D];
__device__ __half g_h16[(size_t)N_NODES * D];
__device__ __half g_B16[256 * D];   // folded weights, k-major: B[k][j], fp16
__device__ float  g_br[D];          // folded bias (fp32)
__device__ float  g_bnsum[D];
__device__ float  g_bnsq[D];

// ---------------- K0: zero counters + BN stats -------------------------------
#define ZTOTAL (2 * N_NODES + 2 * D)
__global__ void k_zero() {
    int idx = blockIdx.x * blockDim.x + threadIdx.x;
    if (idx < N_NODES) g_cnt[idx] = 0;
    else if (idx < 2 * N_NODES) g_cur[idx - N_NODES] = 0;
    else if (idx < 2 * N_NODES + D) g_bnsum[idx - 2 * N_NODES] = 0.f;
    else if (idx < ZTOTAL) g_bnsq[idx - 2 * N_NODES - D] = 0.f;
}

// ---------------- K1: degree count (1 edge/thread) + weight fold + x->fp16 ---
// The count range is atomic-latency-bound with idle issue slots; the fold and
// convert ranges ride along in the same grid and overlap with it.
#define BFOLD     (256 * D)                      // 32768
#define X4_TOTAL  ((N_NODES * D) / 4)            // 1600000
#define FC_TOTAL  (N_EDGES + BFOLD + D + X4_TOTAL)
__global__ void k_count_fold(const int* __restrict__ dst,
                             const float* __restrict__ x,
                             const float* __restrict__ Wrel,
                             const float* __restrict__ brel,
                             const float* __restrict__ Wroot) {
    int idx = blockIdx.x * blockDim.x + threadIdx.x;
    if (idx < N_EDGES) {
        atomicAdd(&g_cnt[dst[idx]], 1);
    } else if (idx < N_EDGES + BFOLD) {
        int e = idx - N_EDGES;
        int k = e >> 7;          // 0..255 (A column)
        int j = e & 127;         // output feature
        float s = 0.f;
        if (k < D) {             // x half pairs with W_root
            #pragma unroll
            for (int c = 0; c < N_CONVS; c++) s += Wroot[c * D * D + j * D + k];
        } else {                 // agg half pairs with W_rel
            int kk = k - D;
            #pragma unroll
            for (int c = 0; c < N_CONVS; c++) s += Wrel[c * D * D + j * D + kk];
        }
        g_B16[e] = __float2half_rn(s);
    } else if (idx < N_EDGES + BFOLD + D) {
        int j = idx - (N_EDGES + BFOLD);
        float s = 0.f;
        #pragma unroll
        for (int c = 0; c < N_CONVS; c++) s += brel[c * D + j];
        g_br[j] = s;
    } else if (idx < FC_TOTAL) {
        int e4 = idx - (N_EDGES + BFOLD + D);
        float4 v = ((const float4*)x)[e4];
        __half2* o = (__half2*)g_x16;
        o[e4 * 2]     = __floats2half2_rn(v.x, v.y);
        o[e4 * 2 + 1] = __floats2half2_rn(v.z, v.w);
    }
}

// ---------------- K2: exclusive scan (single CTA, coalesced warp chunks) -----
__global__ void k_scan() {
    __shared__ int wsum[32];
    const int t = threadIdx.x;          // 1024 threads = 32 warps
    const int w = t >> 5, lane = t & 31;
    const int CHUNK = 1568;             // 32*1568 = 50176 >= 50000
    const int base = w * CHUNK;

    int tot = 0;
    for (int i = lane; i < CHUNK; i += 32) {
        int idx = base + i;
        tot += (idx < N_NODES) ? g_cnt[idx] : 0;
    }
    #pragma unroll
    for (int d = 16; d; d >>= 1) tot += __shfl_down_sync(0xffffffffu, tot, d);
    if (lane == 0) wsum[w] = tot;
    __syncthreads();

    if (w == 0) {
        int v = wsum[lane];
        int incl = v;
        #pragma unroll
        for (int d = 1; d < 32; d <<= 1) {
            int u = __shfl_up_sync(0xffffffffu, incl, d);
            if (lane >= d) incl += u;
        }
        wsum[lane] = incl - v;          // exclusive warp base
        if (lane == 31) g_off[N_NODES] = incl;
    }
    __syncthreads();

    int run = wsum[w];
    for (int i = lane; i < CHUNK; i += 32) {
        int idx = base + i;
        int v = (idx < N_NODES) ? g_cnt[idx] : 0;
        int incl = v;
        #pragma unroll
        for (int d = 1; d < 32; d <<= 1) {
            int u = __shfl_up_sync(0xffffffffu, incl, d);
            if (lane >= d) incl += u;
        }
        if (idx < N_NODES) g_off[idx] = run + incl - v;
        run += __shfl_sync(0xffffffffu, incl, 31);
    }
}

// ---------------- K3: scatter edges into CSR (1 edge/thread) -----------------
__global__ void k_scatter(const int* __restrict__ src, const int* __restrict__ dst) {
    int i = blockIdx.x * blockDim.x + threadIdx.x;
    if (i < N_EDGES) {
        int d = dst[i];
        int p = g_off[d] + atomicAdd(&g_cur[d], 1);
        g_ssrc[p] = src[i];
    }
}

// ---------------- K4: aggregate (warp per node, uint2 loads, fp16 out) -------
__global__ void k_agg() {
    int warp = (blockIdx.x * blockDim.x + threadIdx.x) >> 5;
    int lane = threadIdx.x & 31;
    if (warp >= N_NODES) return;
    int e0 = g_off[warp], e1 = g_off[warp + 1];
    float acc[4];
    acc[0] = acc[1] = acc[2] = acc[3] = 0.f;
    for (int b = e0; b < e1; b += 32) {
        int cnt = min(32, e1 - b);
        int s = (lane < cnt) ? g_ssrc[b + lane] : 0;
        #pragma unroll 4
        for (int j = 0; j < cnt; j++) {
            int sj = __shfl_sync(0xffffffffu, s, j);
            uint2 raw = *(const uint2*)(g_x16 + (size_t)sj * D + lane * 4);
            float2 f0 = __half22float2(*(__half2*)&raw.x);
            float2 f1 = __half22float2(*(__half2*)&raw.y);
            acc[0] += f0.x; acc[1] += f0.y; acc[2] += f1.x; acc[3] += f1.y;
        }
    }
    __half2 h0 = __floats2half2_rn(acc[0], acc[1]);
    __half2 h1 = __floats2half2_rn(acc[2], acc[3]);
    uint2 o;
    o.x = *(u32*)&h0; o.y = *(u32*)&h1;
    *(uint2*)(g_agg16 + (size_t)warp * D + lane * 4) = o;
}

// ---------------- K5: HMMA GEMM  h16 = [x16|agg16] @ B16 + br, + BN stats ----
#define BS_ROWPAD 136               // halves per B row (128 + 8)
#define AS_ROWPAD 72                // halves per A row (64 + 8)
#define BS_BYTES  (256 * BS_ROWPAD * 2)          // 69632
#define AS_BYTES  (2 * 128 * AS_ROWPAD * 2)      // 36864
#define GEMM_SMEM (BS_BYTES + AS_BYTES)          // 106496

__device__ __forceinline__ void ldsm4(u32& r0, u32& r1, u32& r2, u32& r3, u32 a) {
    asm volatile("ldmatrix.sync.aligned.m8n8.x4.shared.b16 {%0,%1,%2,%3}, [%4];"
                 : "=r"(r0), "=r"(r1), "=r"(r2), "=r"(r3) : "r"(a));
}
__device__ __forceinline__ void ldsm4t(u32& r0, u32& r1, u32& r2, u32& r3, u32 a) {
    asm volatile("ldmatrix.sync.aligned.m8n8.x4.trans.shared.b16 {%0,%1,%2,%3}, [%4];"
                 : "=r"(r0), "=r"(r1), "=r"(r2), "=r"(r3) : "r"(a));
}
__device__ __forceinline__ void mma16816(float* c, u32 a0, u32 a1, u32 a2, u32 a3,
                                         u32 b0, u32 b1) {
    asm volatile("mma.sync.aligned.m16n8k16.row.col.f32.f16.f16.f32 "
                 "{%0,%1,%2,%3}, {%4,%5,%6,%7}, {%8,%9}, {%0,%1,%2,%3};"
                 : "+f"(c[0]), "+f"(c[1]), "+f"(c[2]), "+f"(c[3])
                 : "r"(a0), "r"(a1), "r"(a2), "r"(a3), "r"(b0), "r"(b1));
}
__device__ __forceinline__ void cpasync16(u32 saddr, const void* gptr, int zfill) {
    asm volatile("cp.async.cg.shared.global [%0], [%1], 16, %2;"
                 :: "r"(saddr), "l"(gptr), "r"(zfill));
}
__device__ __forceinline__ void cpasync_commit() {
    asm volatile("cp.async.commit_group;");
}
__device__ __forceinline__ void cpasync_wait0() {
    asm volatile("cp.async.wait_group 0;");
}

extern __shared__ char dynsm[];

__global__ __launch_bounds__(256, 2) void k_gemm() {
    __half* Bs = (__half*)dynsm;
    __half* As = (__half*)(dynsm + BS_BYTES);

    const int tid  = threadIdx.x;
    const int lane = tid & 31;
    const int wid  = tid >> 5;
    const int wm   = wid >> 1;      // 0..3
    const int wn   = wid & 1;       // 0..1
    const int m0   = blockIdx.x * 128;

    // ---- A stage copier: stage s covers k in [64s, 64s+64), cp.async 16B ----
    auto issueA = [&](int s, int buf) {
        const __half* src = (s < 2) ? g_x16 : g_agg16;
        int ko = (s < 2) ? s * 64 : (s - 2) * 64;
        #pragma unroll
        for (int j = 0; j < 4; j++) {
            int i = tid + j * 256;          // 1024 16B-chunks total
            int row = i >> 3, c = i & 7;
            int r = m0 + row;
            u32 saddr = (u32)__cvta_generic_to_shared(
                As + buf * 128 * AS_ROWPAD + row * AS_ROWPAD + c * 8);
            const void* g = src + (size_t)r * D + ko + c * 8;
            cpasync16(saddr, g, (r < N_NODES) ? 16 : 0);
        }
    };

    // prologue: start A stage 0, then load B while it flies
    issueA(0, 0);
    cpasync_commit();

    // ---- load full B (256 x 128 halves) into padded smem ----
    #pragma unroll
    for (int j = 0; j < 16; j++) {
        int i = tid + j * 256;              // 4096 float4 total
        int row = i >> 4, c = i & 15;
        float4 v = *(const float4*)(g_B16 + row * D + c * 8);
        *(float4*)(Bs + row * BS_ROWPAD + c * 8) = v;
    }

    cpasync_wait0();
    __syncthreads();

    // ---- per-lane ldmatrix addresses ----
    const int m_off = ((lane >> 3) & 1) * 8 + (lane & 7);
    const int k_off = (lane >> 4) * 8;
    const int kb_off = m_off;
    const int n_off = k_off;

    u32 a_base0 = (u32)__cvta_generic_to_shared(
        As + (wm * 32 + m_off) * AS_ROWPAD + k_off);
    u32 b_base = (u32)__cvta_generic_to_shared(
        Bs + kb_off * BS_ROWPAD + wn * 64 + n_off);

    float acc[2][8][4];
    #pragma unroll
    for (int mt = 0; mt < 2; mt++)
        #pragma unroll
        for (int nt = 0; nt < 8; nt++)
            #pragma unroll
            for (int q = 0; q < 4; q++) acc[mt][nt][q] = 0.f;

    #pragma unroll 1
    for (int s = 0; s < 4; s++) {
        const int buf = s & 1;
        if (s < 3) {                 // kick next-stage copy; overlaps with MMA
            issueA(s + 1, buf ^ 1);
            cpasync_commit();
        }
        const u32 a_stage = a_base0 + buf * (128 * AS_ROWPAD * 2);

        #pragma unroll
        for (int k16 = 0; k16 < 4; k16++) {
            u32 a[2][4];
            #pragma unroll
            for (int mt = 0; mt < 2; mt++)
                ldsm4(a[mt][0], a[mt][1], a[mt][2], a[mt][3],
                      a_stage + (mt * 16) * (AS_ROWPAD * 2) + k16 * 32);
            const u32 b_k = b_base + (s * 64 + k16 * 16) * (BS_ROWPAD * 2);
            #pragma unroll
            for (int np = 0; np < 4; np++) {
                u32 b0, b1, b2, b3;
                ldsm4t(b0, b1, b2, b3, b_k + np * 32);
                #pragma unroll
                for (int mt = 0; mt < 2; mt++) {
                    mma16816(acc[mt][np * 2],     a[mt][0], a[mt][1], a[mt][2], a[mt][3], b0, b1);
                    mma16816(acc[mt][np * 2 + 1], a[mt][0], a[mt][1], a[mt][2], a[mt][3], b2, b3);
                }
            }
        }
        if (s < 3) {
            cpasync_wait0();
            __syncthreads();
        }
    }

    // ---- epilogue: bias, store h16, BN partial stats (fp32, pre-rounding) ---
    const int qr = lane >> 2;     // 0..7
    const int qc = lane & 3;      // 0..3
    float s16[16], q16[16];
    #pragma unroll
    for (int t = 0; t < 16; t++) { s16[t] = 0.f; q16[t] = 0.f; }

    #pragma unroll
    for (int nt = 0; nt < 8; nt++) {
        const int col = wn * 64 + nt * 8 + qc * 2;
        const float2 br = *(const float2*)(g_br + col);
        #pragma unroll
        for (int mt = 0; mt < 2; mt++) {
            #pragma unroll
            for (int hh = 0; hh < 2; hh++) {   // c0c1 row, c2c3 row (+8)
                int r = m0 + wm * 32 + mt * 16 + qr + hh * 8;
                if (r >= N_NODES) continue;
                float v0 = acc[mt][nt][hh * 2]     + br.x;
                float v1 = acc[mt][nt][hh * 2 + 1] + br.y;
                *(__half2*)(g_h16 + (size_t)r * D + col) = __floats2half2_rn(v0, v1);
                s16[nt * 2]     += v0;  q16[nt * 2]     += v0 * v0;
                s16[nt * 2 + 1] += v1;  q16[nt * 2 + 1] += v1 * v1;
            }
        }
    }

    // ---- reduce stats: smem atomics then one global atomic per col ----
    __syncthreads();                 // all reads of As done; reuse as scratch
    float* sm_s = (float*)(dynsm + BS_BYTES);
    float* sm_q = sm_s + D;
    if (tid < D) { sm_s[tid] = 0.f; sm_q[tid] = 0.f; }
    __syncthreads();
    #pragma unroll
    for (int nt = 0; nt < 8; nt++) {
        int col = wn * 64 + nt * 8 + qc * 2;
        atomicAdd(&sm_s[col], s16[nt * 2]);
        atomicAdd(&sm_q[col], q16[nt * 2]);
        atomicAdd(&sm_s[col + 1], s16[nt * 2 + 1]);
        atomicAdd(&sm_q[col + 1], q16[nt * 2 + 1]);
    }
    __syncthreads();
    if (tid < D) {
        atomicAdd(&g_bnsum[tid], sm_s[tid]);
        atomicAdd(&g_bnsq[tid], sm_q[tid]);
    }
}

// ---------------- K6: BN finalize + per-graph pool + relu + classifier -------
__global__ void k_final(const int* __restrict__ batch,
                        const float* __restrict__ gamma, const float* __restrict__ beta,
                        const float* __restrict__ Wc, const float* __restrict__ bc,
                        float* __restrict__ out) {
    __shared__ float ps[D];
    const int g = blockIdx.x;
    const int f = threadIdx.x;       // 128 threads

    float mean = g_bnsum[f] * (1.f / N_NODES);
    float var  = g_bnsq[f] * (1.f / N_NODES) - mean * mean;
    float sc   = gamma[f] * rsqrtf(var + EPS);
    float sh   = beta[f] - mean * sc;

    int lo = 0, hi = N_NODES;
    while (lo < hi) { int mid = (lo + hi) >> 1; if (batch[mid] < g) lo = mid + 1; else hi = mid; }
    int start = lo;
    hi = N_NODES;
    while (lo < hi) { int mid = (lo + hi) >> 1; if (batch[mid] < g + 1) lo = mid + 1; else hi = mid; }
    int end = lo;

    const float NEG_INF = __int_as_float(0xff800000);
    float mx = NEG_INF, mn = -NEG_INF;
    for (int n = start; n < end; n++) {
        float v = __half2float(g_h16[(size_t)n * D + f]);
        mx = fmaxf(mx, v); mn = fminf(mn, v);
    }

    float v;
    if (start == end) {
        v = 0.f;                     // empty segment: relu(-inf) = 0
    } else {
        float t = (sc >= 0.f) ? mx : mn;   // max-pool commutes with monotone affine
        v = fmaxf(fmaf(sc, t, sh), 0.f);
    }
    ps[f] = v;
    __syncthreads();

    if (f < 96) {
        float acc = bc[f];
        const float4* w = (const float4*)(Wc + f * D);
        const float4* p = (const float4*)ps;
        #pragma unroll
        for (int k = 0; k < D / 4; k++) {
            float4 wv = w[k], pv = p[k];
            acc += wv.x * pv.x + wv.y * pv.y + wv.z * pv.z + wv.w * pv.w;
        }
        out[g * 96 + f] = acc;
    }
}

// ---------------- launch ------------------------------------------------------
extern "C" void kernel_launch(void* const* d_in, const int* in_sizes, int n_in,
                              void* d_out, int out_size) {
    const float* x     = (const float*)d_in[0];
    const int*   ei    = (const int*)d_in[1];   // [2, N_EDGES]: src then dst
    const int*   batch = (const int*)d_in[2];
    /* d_in[3] = i (unused, i=0 branch) */
    const float* Wrel  = (const float*)d_in[4];
    const float* brel  = (const float*)d_in[5];
    const float* Wroot = (const float*)d_in[6];
    const float* gamma = (const float*)d_in[7];
    const float* beta  = (const float*)d_in[8];
    const float* Wc    = (const float*)d_in[9];
    const float* bc    = (const float*)d_in[10];
    float* out = (float*)d_out;

    const int* src = ei;
    const int* dst = ei + N_EDGES;

    static int smem_set = 0;
    if (!smem_set) {
        cudaFuncSetAttribute(k_gemm, cudaFuncAttributeMaxDynamicSharedMemorySize,
                             GEMM_SMEM);
        smem_set = 1;
    }

    k_zero<<<(ZTOTAL + 255) / 256, 256>>>();
    k_count_fold<<<(FC_TOTAL + 255) / 256, 256>>>(dst, x, Wrel, brel, Wroot);
    k_scan<<<1, 1024>>>();
    k_scatter<<<(N_EDGES + 255) / 256, 256>>>(src, dst);
    k_agg<<<(N_NODES * 32 + 255) / 256, 256>>>();
    k_gemm<<<(N_NODES + 127) / 128, 256, GEMM_SMEM>>>();
    k_final<<<N_GRAPHS, 128>>>(batch, gamma, beta, Wc, bc, out);
}